// round 16
// baseline (speedup 1.0000x reference)
#include <cuda_runtime.h>
#include <math.h>

#define B_    64
#define H_    8
#define N_    16384
#define M_    64
#define C_    1024
#define IVH_  198          // 3*M + 6
#define HIVH  (H_ * IVH_)  // 1584
#define BH_   (B_ * H_)    // 512
#define PITCH 68           // floats; 17x16B rows -> conflict-free float4
#define TILE_R 256
#define NCHUNK 32
#define CHUNK_N (N_ / NCHUNK)  // 512
#define KSPLIT 8

// ---------------- scratch (device globals; no allocation allowed) ----------
__device__ float  g_ivp[KSPLIT][B_ * HIVH];
__device__ float  g_k[BH_ * M_];
__device__ float  g_par[BH_ * 8];            // beta, g, s0, s1, s2, gamma, knorm
__device__ float  g_es[BH_ * NCHUNK];        // per-chunk expsum (no shift)
__device__ float  g_partial[NCHUNK * BH_ * M_];

__device__ __forceinline__ void cp_async16(void* dst, const void* src) {
    unsigned d = (unsigned)__cvta_generic_to_shared(dst);
    asm volatile("cp.async.cg.shared.global [%0], [%1], 16;" :: "r"(d), "l"(src));
}

// ---------------- kernel 0: profile-slot shifter (no-op) --------------------
__global__ void k_nop() {}

// ---------------- kernel 1: iv partials = x @ W  (K-split by 8) ------------
__global__ __launch_bounds__(256) void k_gemm(const float* __restrict__ x,
                                              const float* __restrict__ W) {
    __shared__ float xs[64][33];
    __shared__ float ws[32][33];
    int c0  = blockIdx.x * 32;
    int ks  = blockIdx.y;
    int col = threadIdx.x & 31;
    int rg  = threadIdx.x >> 5;
    float acc[8];
#pragma unroll
    for (int j = 0; j < 8; j++) acc[j] = 0.f;

    int k0 = ks * (C_ / KSPLIT);
    for (int kc = k0; kc < k0 + C_ / KSPLIT; kc += 32) {
#pragma unroll
        for (int i = 0; i < 8; i++) {
            int idx = threadIdx.x + i * 256;
            int r = idx >> 5, kk = idx & 31;
            xs[r][kk] = x[r * C_ + kc + kk];
        }
#pragma unroll
        for (int i = 0; i < 4; i++) {
            int idx = threadIdx.x + i * 256;
            int rr = idx >> 5, cc = idx & 31;
            int c = c0 + cc;
            ws[rr][cc] = (c < HIVH) ? W[(size_t)(kc + rr) * HIVH + c] : 0.f;
        }
        __syncthreads();
#pragma unroll
        for (int k = 0; k < 32; k++) {
            float wv = ws[k][col];
#pragma unroll
            for (int j = 0; j < 8; j++)
                acc[j] = fmaf(xs[j * 8 + rg][k], wv, acc[j]);
        }
        __syncthreads();
    }
    int c = c0 + col;
    if (c < HIVH) {
#pragma unroll
        for (int j = 0; j < 8; j++)
            g_ivp[ks][(size_t)(j * 8 + rg) * HIVH + c] = acc[j];
    }
}

// ---------------- kernel 2: reduce K-split + activations -------------------
__device__ __forceinline__ float iv_sum(int b, int off, const float* bias) {
    float s = bias[off];
#pragma unroll
    for (int ks = 0; ks < KSPLIT; ks++) s += g_ivp[ks][(size_t)b * HIVH + off];
    return s;
}

__global__ __launch_bounds__(64) void k_act(const float* __restrict__ bias,
                                            float* __restrict__ out_e,
                                            float* __restrict__ out_a) {
    int bh = blockIdx.x;
    int b = bh >> 3, h = bh & 7;
    int base = h * IVH_;
    int t = threadIdx.x;
    __shared__ float red[2];

    float kv = iv_sum(b, base + t, bias);
    g_k[(size_t)bh * M_ + t] = kv;
    float sq = kv * kv;
#pragma unroll
    for (int o = 16; o; o >>= 1) sq += __shfl_xor_sync(0xffffffffu, sq, o);
    if ((t & 31) == 0) red[t >> 5] = sq;

    float e_in = iv_sum(b, base + M_ + 6 + t, bias);
    out_e[(size_t)bh * M_ + t] = 1.f / (1.f + __expf(-e_in));
    out_a[(size_t)bh * M_ + t] = iv_sum(b, base + 2 * M_ + 6 + t, bias);
    __syncthreads();

    if (t == 0) {
        float knorm = sqrtf(red[0] + red[1]);
        float bx = iv_sum(b, base + M_, bias);
        float beta = (bx > 20.f) ? bx : log1pf(expf(bx));
        float g = 1.f / (1.f + expf(-iv_sum(b, base + M_ + 1, bias)));
        float s0 = iv_sum(b, base + M_ + 2, bias);
        float s1 = iv_sum(b, base + M_ + 3, bias);
        float s2 = iv_sum(b, base + M_ + 4, bias);
        float mx = fmaxf(s0, fmaxf(s1, s2));
        float e0 = expf(s0 - mx), e1 = expf(s1 - mx), e2 = expf(s2 - mx);
        float inv = 1.f / (e0 + e1 + e2);
        float gx = iv_sum(b, base + M_ + 5, bias);
        float gamma = 1.f + ((gx > 20.f) ? gx : log1pf(expf(gx)));
        float* p = g_par + (size_t)bh * 8;
        p[0] = beta; p[1] = g; p[2] = e0 * inv; p[3] = e1 * inv;
        p[4] = e2 * inv; p[5] = gamma; p[6] = knorm;
    }
}

// ---------------- kernel 3: exp(logits) + per-chunk expsum (cp.async) ------
__global__ __launch_bounds__(256) void k_cos(const float* __restrict__ mem,
                                             float* __restrict__ wc_buf) {
    extern __shared__ float tile[];          // TILE_R * PITCH floats
    __shared__ float ksh[8][64];
    __shared__ float p_ratio[8];             // beta / knorm
    __shared__ float red_s[8][8];
    int b = blockIdx.y, chunk = blockIdx.x;
    int tid = threadIdx.x;
    int w = tid >> 5, lane = tid & 31;

    for (int i = tid; i < 512; i += 256) ksh[i >> 6][i & 63] = g_k[(size_t)b * 512 + i];
    if (tid < 8) {
        const float* p = g_par + ((size_t)b * 8 + tid) * 8;
        p_ratio[tid] = __fdividef(p[0], p[6]);   // beta / knorm
    }
    __syncthreads();

    float sloc[8];
#pragma unroll
    for (int h = 0; h < 8; h++) sloc[h] = 0.f;

    for (int st = 0; st < CHUNK_N; st += TILE_R) {
        int n0 = chunk * CHUNK_N + st;
        const float* src = mem + ((size_t)b * N_ + n0) * M_;
#pragma unroll
        for (int i = 0; i < 16; i++) {
            int idx = tid + i * 256;
            int r = idx >> 4, c4 = idx & 15;
            cp_async16(tile + r * PITCH + c4 * 4, src + r * M_ + c4 * 4);
        }
        asm volatile("cp.async.commit_group;");
        asm volatile("cp.async.wait_group 0;");
        __syncthreads();

        float acc[8];
#pragma unroll
        for (int h = 0; h < 8; h++) acc[h] = 0.f;
        float nn = 0.f;
        const float* row = tile + tid * PITCH;
#pragma unroll
        for (int m = 0; m < 64; m += 4) {
            float4 v = *(const float4*)(row + m);
            nn = fmaf(v.x, v.x, nn); nn = fmaf(v.y, v.y, nn);
            nn = fmaf(v.z, v.z, nn); nn = fmaf(v.w, v.w, nn);
#pragma unroll
            for (int h = 0; h < 8; h++) {
                float4 kv = *(const float4*)(&ksh[h][m]);
                acc[h] = fmaf(v.x, kv.x, acc[h]);
                acc[h] = fmaf(v.y, kv.y, acc[h]);
                acc[h] = fmaf(v.z, kv.z, acc[h]);
                acc[h] = fmaf(v.w, kv.w, acc[h]);
            }
        }
        float rinv = __frsqrt_rn(nn);            // 1/||mem_n||
        int n = n0 + tid;
#pragma unroll
        for (int h = 0; h < 8; h++) {
            float l = p_ratio[h] * acc[h] * rinv;
            float e = __expf(l);
            wc_buf[((size_t)(b * 8 + h)) * N_ + n] = e;   // store exp-space
            sloc[h] += e;
        }
        __syncthreads();
    }

#pragma unroll
    for (int o = 16; o; o >>= 1) {
#pragma unroll
        for (int h = 0; h < 8; h++)
            sloc[h] += __shfl_xor_sync(0xffffffffu, sloc[h], o);
    }
    if (lane == 0) {
#pragma unroll
        for (int h = 0; h < 8; h++) red_s[w][h] = sloc[h];
    }
    __syncthreads();
    if (tid < 8) {
        float s = 0.f;
#pragma unroll
        for (int ww = 0; ww < 8; ww++) s += red_s[ww][tid];
        g_es[((size_t)b * 8 + tid) * NCHUNK + chunk] = s;
    }
}

// ---------------- kernel 4: addressing (proven form, exp-space input) ------
__global__ __launch_bounds__(512) void k_addr(float* __restrict__ wbuf,
                                              const float* __restrict__ wprev) {
    extern __shared__ float sw[];            // N_ floats (wg)
    __shared__ float red[16];
    __shared__ float sS;
    int bh = blockIdx.x;
    int tid = threadIdx.x;
    const float* par = g_par + (size_t)bh * 8;
    float gg = par[1], s0 = par[2], s1 = par[3], s2 = par[4], gamma = par[5];

    if (tid < 32) {
        float S = g_es[(size_t)bh * NCHUNK + tid];   // NCHUNK == 32
#pragma unroll
        for (int o = 16; o; o >>= 1) S += __shfl_xor_sync(0xffffffffu, S, o);
        if (tid == 0) sS = S;
    }
    __syncthreads();
    float ginvS = gg / sS;
    float gc = 1.f - gg;

    float* lrow = wbuf + (size_t)bh * N_;
    const float* wprow = wprev + (size_t)bh * N_;

#pragma unroll 4
    for (int i = 0; i < 32; i++) {
        int n = tid + i * 512;
        sw[n] = fmaf(ginvS, lrow[n], gc * wprow[n]);
    }
    __syncthreads();

    float wp[32];
    float lsum = 0.f;
#pragma unroll 4
    for (int i = 0; i < 32; i++) {
        int n = tid + i * 512;
        int nm = (n + N_ - 1) & (N_ - 1);
        int np = (n + 1) & (N_ - 1);
        float ws = s0 * sw[nm] + s1 * sw[n] + s2 * sw[np];
        float v = exp2f(gamma * __log2f(ws));
        wp[i] = v;
        lsum += v;
    }
#pragma unroll
    for (int o = 16; o; o >>= 1) lsum += __shfl_xor_sync(0xffffffffu, lsum, o);
    int w = tid >> 5, l = tid & 31;
    if (l == 0) red[w] = lsum;
    __syncthreads();
    if (w == 0) {
        float v = (l < 16) ? red[l] : 0.f;
#pragma unroll
        for (int o = 8; o; o >>= 1) v += __shfl_xor_sync(0xffffffffu, v, o);
        if (l == 0) red[0] = v;
    }
    __syncthreads();
    float inv = 1.f / (red[0] + 1e-16f);

#pragma unroll 4
    for (int i = 0; i < 32; i++)
        lrow[tid + i * 512] = wp[i] * inv;
}

// ---------------- kernel 5: read partials (transposed w stage, LDS.128) ----
__global__ __launch_bounds__(256) void k_read(const float* __restrict__ mem,
                                              const float* __restrict__ wbuf) {
    __shared__ __align__(16) float wshT[512][12];   // [n][h] 48B rows, 24 KB
    __shared__ float red[8][512];
    int b = blockIdx.y, chunk = blockIdx.x;
    int tid = threadIdx.x;
    int w = tid >> 5, lane = tid & 31;
    float2 acc[8];
#pragma unroll
    for (int h = 0; h < 8; h++) acc[h] = make_float2(0.f, 0.f);

    const float2* mrow = (const float2*)(mem + ((size_t)b * N_ + (size_t)chunk * CHUNK_N) * M_);

#pragma unroll
    for (int i = 0; i < 16; i++) {
        int idx = tid + i * 256;
        int hh = idx >> 9, nn = idx & 511;
        wshT[nn][hh] = wbuf[((size_t)(b * 8 + hh)) * N_ + chunk * CHUNK_N + nn];
    }
    __syncthreads();

#pragma unroll 4
    for (int j = 0; j < 64; j++) {
        int nl = w * 64 + j;
        float2 mv = mrow[(size_t)nl * 32 + lane];
        float4 wa = *(const float4*)(&wshT[nl][0]);  // heads 0-3 (broadcast)
        float4 wb = *(const float4*)(&wshT[nl][4]);  // heads 4-7 (broadcast)
        acc[0].x = fmaf(wa.x, mv.x, acc[0].x); acc[0].y = fmaf(wa.x, mv.y, acc[0].y);
        acc[1].x = fmaf(wa.y, mv.x, acc[1].x); acc[1].y = fmaf(wa.y, mv.y, acc[1].y);
        acc[2].x = fmaf(wa.z, mv.x, acc[2].x); acc[2].y = fmaf(wa.z, mv.y, acc[2].y);
        acc[3].x = fmaf(wa.w, mv.x, acc[3].x); acc[3].y = fmaf(wa.w, mv.y, acc[3].y);
        acc[4].x = fmaf(wb.x, mv.x, acc[4].x); acc[4].y = fmaf(wb.x, mv.y, acc[4].y);
        acc[5].x = fmaf(wb.y, mv.x, acc[5].x); acc[5].y = fmaf(wb.y, mv.y, acc[5].y);
        acc[6].x = fmaf(wb.z, mv.x, acc[6].x); acc[6].y = fmaf(wb.z, mv.y, acc[6].y);
        acc[7].x = fmaf(wb.w, mv.x, acc[7].x); acc[7].y = fmaf(wb.w, mv.y, acc[7].y);
    }
    __syncthreads();
#pragma unroll
    for (int h = 0; h < 8; h++) {
        red[w][h * 64 + lane * 2]     = acc[h].x;
        red[w][h * 64 + lane * 2 + 1] = acc[h].y;
    }
    __syncthreads();
#pragma unroll
    for (int r = 0; r < 2; r++) {
        int i = tid + r * 256;
        float s = 0.f;
#pragma unroll
        for (int ww = 0; ww < 8; ww++) s += red[ww][i];
        g_partial[((size_t)chunk * B_ + b) * 512 + i] = s;
    }
}

// ---------------- kernel 6: reduce partials -> read_data --------------------
__global__ __launch_bounds__(256) void k_final(float* __restrict__ out) {
    int i = blockIdx.x * 256 + threadIdx.x;  // < 32768
    float s = 0.f;
#pragma unroll
    for (int c = 0; c < NCHUNK; c++)
        s += g_partial[(size_t)c * BH_ * M_ + i];
    out[i] = s;
}

// ---------------- launch -----------------------------------------------------
extern "C" void kernel_launch(void* const* d_in, const int* in_sizes, int n_in,
                              void* d_out, int out_size) {
    const float* x     = (const float*)d_in[0];
    const float* mem   = (const float*)d_in[1];
    const float* wprev = (const float*)d_in[2];
    const float* W     = (const float*)d_in[3];
    const float* bias  = (const float*)d_in[4];
    float* out = (float*)d_out;
    float* out_read = out;                         // 32768
    float* out_w    = out + 32768;                 // 8388608
    float* out_e    = out + 32768 + (size_t)BH_ * N_;
    float* out_a    = out_e + 32768;

    cudaFuncSetAttribute(k_cos,  cudaFuncAttributeMaxDynamicSharedMemorySize, TILE_R * PITCH * 4);
    cudaFuncSetAttribute(k_addr, cudaFuncAttributeMaxDynamicSharedMemorySize, N_ * 4);

    k_nop<<<1, 32>>>();   // keeps the fixed ncu capture slot on k_cos
    k_gemm<<<dim3(50, KSPLIT), 256>>>(x, W);
    k_act<<<BH_, 64>>>(bias, out_e, out_a);
    k_cos<<<dim3(NCHUNK, B_), 256, TILE_R * PITCH * 4>>>(mem, out_w);
    k_addr<<<BH_, 512, N_ * 4>>>(out_w, wprev);
    k_read<<<dim3(NCHUNK, B_), 256>>>(mem, out_w);
    k_final<<<128, 256>>>(out_read);
}

// round 17
// speedup vs baseline: 1.3416x; 1.3416x over previous
#include <cuda_runtime.h>
#include <math.h>

#define B_    64
#define H_    8
#define N_    16384
#define M_    64
#define C_    1024
#define IVH_  198          // 3*M + 6
#define HIVH  (H_ * IVH_)  // 1584
#define BH_   (B_ * H_)    // 512
#define PITCH 68           // floats; 17x16B rows -> conflict-free float4
#define TILE_R 256
#define NCHUNK 32
#define CHUNK_N (N_ / NCHUNK)  // 512
#define KSPLIT 8

// ---------------- scratch (device globals; no allocation allowed) ----------
__device__ float  g_ivp[KSPLIT][B_ * HIVH];
__device__ float  g_k[BH_ * M_];
__device__ float  g_par[BH_ * 8];            // beta, g, s0, s1, s2, gamma, knorm
__device__ float  g_es[BH_ * NCHUNK];        // per-chunk expsum (no shift)
__device__ float  g_partial[NCHUNK * BH_ * M_];

__device__ __forceinline__ void cp_async16(void* dst, const void* src) {
    unsigned d = (unsigned)__cvta_generic_to_shared(dst);
    asm volatile("cp.async.cg.shared.global [%0], [%1], 16;" :: "r"(d), "l"(src));
}

// ---------------- kernel 0: profile-slot shifter (no-op) --------------------
__global__ void k_nop() {}

// ---------------- kernel 1: iv partials = x @ W  (K-split by 8) ------------
__global__ __launch_bounds__(256) void k_gemm(const float* __restrict__ x,
                                              const float* __restrict__ W) {
    __shared__ float xs[64][33];
    __shared__ float ws[32][33];
    int c0  = blockIdx.x * 32;
    int ks  = blockIdx.y;
    int col = threadIdx.x & 31;
    int rg  = threadIdx.x >> 5;
    float acc[8];
#pragma unroll
    for (int j = 0; j < 8; j++) acc[j] = 0.f;

    int k0 = ks * (C_ / KSPLIT);
    for (int kc = k0; kc < k0 + C_ / KSPLIT; kc += 32) {
#pragma unroll
        for (int i = 0; i < 8; i++) {
            int idx = threadIdx.x + i * 256;
            int r = idx >> 5, kk = idx & 31;
            xs[r][kk] = x[r * C_ + kc + kk];
        }
#pragma unroll
        for (int i = 0; i < 4; i++) {
            int idx = threadIdx.x + i * 256;
            int rr = idx >> 5, cc = idx & 31;
            int c = c0 + cc;
            ws[rr][cc] = (c < HIVH) ? W[(size_t)(kc + rr) * HIVH + c] : 0.f;
        }
        __syncthreads();
#pragma unroll
        for (int k = 0; k < 32; k++) {
            float wv = ws[k][col];
#pragma unroll
            for (int j = 0; j < 8; j++)
                acc[j] = fmaf(xs[j * 8 + rg][k], wv, acc[j]);
        }
        __syncthreads();
    }
    int c = c0 + col;
    if (c < HIVH) {
#pragma unroll
        for (int j = 0; j < 8; j++)
            g_ivp[ks][(size_t)(j * 8 + rg) * HIVH + c] = acc[j];
    }
}

// ---------------- kernel 2: reduce K-split + activations -------------------
__device__ __forceinline__ float iv_sum(int b, int off, const float* bias) {
    float s = bias[off];
#pragma unroll
    for (int ks = 0; ks < KSPLIT; ks++) s += g_ivp[ks][(size_t)b * HIVH + off];
    return s;
}

__global__ __launch_bounds__(64) void k_act(const float* __restrict__ bias,
                                            float* __restrict__ out_e,
                                            float* __restrict__ out_a) {
    int bh = blockIdx.x;
    int b = bh >> 3, h = bh & 7;
    int base = h * IVH_;
    int t = threadIdx.x;
    __shared__ float red[2];

    float kv = iv_sum(b, base + t, bias);
    g_k[(size_t)bh * M_ + t] = kv;
    float sq = kv * kv;
#pragma unroll
    for (int o = 16; o; o >>= 1) sq += __shfl_xor_sync(0xffffffffu, sq, o);
    if ((t & 31) == 0) red[t >> 5] = sq;

    float e_in = iv_sum(b, base + M_ + 6 + t, bias);
    out_e[(size_t)bh * M_ + t] = 1.f / (1.f + __expf(-e_in));
    out_a[(size_t)bh * M_ + t] = iv_sum(b, base + 2 * M_ + 6 + t, bias);
    __syncthreads();

    if (t == 0) {
        float knorm = sqrtf(red[0] + red[1]);
        float bx = iv_sum(b, base + M_, bias);
        float beta = (bx > 20.f) ? bx : log1pf(expf(bx));
        float g = 1.f / (1.f + expf(-iv_sum(b, base + M_ + 1, bias)));
        float s0 = iv_sum(b, base + M_ + 2, bias);
        float s1 = iv_sum(b, base + M_ + 3, bias);
        float s2 = iv_sum(b, base + M_ + 4, bias);
        float mx = fmaxf(s0, fmaxf(s1, s2));
        float e0 = expf(s0 - mx), e1 = expf(s1 - mx), e2 = expf(s2 - mx);
        float inv = 1.f / (e0 + e1 + e2);
        float gx = iv_sum(b, base + M_ + 5, bias);
        float gamma = 1.f + ((gx > 20.f) ? gx : log1pf(expf(gx)));
        float* p = g_par + (size_t)bh * 8;
        p[0] = beta; p[1] = g; p[2] = e0 * inv; p[3] = e1 * inv;
        p[4] = e2 * inv; p[5] = gamma; p[6] = knorm;
    }
}

// ---------------- kernel 3: exp(logits) + per-chunk expsum (cp.async) ------
__global__ __launch_bounds__(256) void k_cos(const float* __restrict__ mem,
                                             float* __restrict__ wc_buf) {
    extern __shared__ float tile[];          // TILE_R * PITCH floats
    __shared__ float ksh[8][64];
    __shared__ float p_ratio[8];             // beta / knorm
    __shared__ float red_s[8][8];
    int b = blockIdx.y, chunk = blockIdx.x;
    int tid = threadIdx.x;
    int w = tid >> 5, lane = tid & 31;

    for (int i = tid; i < 512; i += 256) ksh[i >> 6][i & 63] = g_k[(size_t)b * 512 + i];
    if (tid < 8) {
        const float* p = g_par + ((size_t)b * 8 + tid) * 8;
        p_ratio[tid] = __fdividef(p[0], p[6]);   // beta / knorm
    }
    __syncthreads();

    float sloc[8];
#pragma unroll
    for (int h = 0; h < 8; h++) sloc[h] = 0.f;

    for (int st = 0; st < CHUNK_N; st += TILE_R) {
        int n0 = chunk * CHUNK_N + st;
        const float* src = mem + ((size_t)b * N_ + n0) * M_;
#pragma unroll
        for (int i = 0; i < 16; i++) {
            int idx = tid + i * 256;
            int r = idx >> 4, c4 = idx & 15;
            cp_async16(tile + r * PITCH + c4 * 4, src + r * M_ + c4 * 4);
        }
        asm volatile("cp.async.commit_group;");
        asm volatile("cp.async.wait_group 0;");
        __syncthreads();

        float acc[8];
#pragma unroll
        for (int h = 0; h < 8; h++) acc[h] = 0.f;
        float nn = 0.f;
        const float* row = tile + tid * PITCH;
#pragma unroll
        for (int m = 0; m < 64; m += 4) {
            float4 v = *(const float4*)(row + m);
            nn = fmaf(v.x, v.x, nn); nn = fmaf(v.y, v.y, nn);
            nn = fmaf(v.z, v.z, nn); nn = fmaf(v.w, v.w, nn);
#pragma unroll
            for (int h = 0; h < 8; h++) {
                float4 kv = *(const float4*)(&ksh[h][m]);
                acc[h] = fmaf(v.x, kv.x, acc[h]);
                acc[h] = fmaf(v.y, kv.y, acc[h]);
                acc[h] = fmaf(v.z, kv.z, acc[h]);
                acc[h] = fmaf(v.w, kv.w, acc[h]);
            }
        }
        float rinv = __frsqrt_rn(nn);            // 1/||mem_n||
        int n = n0 + tid;
#pragma unroll
        for (int h = 0; h < 8; h++) {
            float l = p_ratio[h] * acc[h] * rinv;
            float e = __expf(l);
            wc_buf[((size_t)(b * 8 + h)) * N_ + n] = e;   // store exp-space
            sloc[h] += e;
        }
        __syncthreads();
    }

#pragma unroll
    for (int o = 16; o; o >>= 1) {
#pragma unroll
        for (int h = 0; h < 8; h++)
            sloc[h] += __shfl_xor_sync(0xffffffffu, sloc[h], o);
    }
    if (lane == 0) {
#pragma unroll
        for (int h = 0; h < 8; h++) red_s[w][h] = sloc[h];
    }
    __syncthreads();
    if (tid < 8) {
        float s = 0.f;
#pragma unroll
        for (int ww = 0; ww < 8; ww++) s += red_s[ww][tid];
        g_es[((size_t)b * 8 + tid) * NCHUNK + chunk] = s;
    }
}

// ---------------- kernel 4: addressing (proven form, exp-space input) ------
__global__ __launch_bounds__(512) void k_addr(float* __restrict__ wbuf,
                                              const float* __restrict__ wprev) {
    extern __shared__ float sw[];            // N_ floats (wg)
    __shared__ float red[16];
    __shared__ float sS;
    int bh = blockIdx.x;
    int tid = threadIdx.x;
    const float* par = g_par + (size_t)bh * 8;
    float gg = par[1], s0 = par[2], s1 = par[3], s2 = par[4], gamma = par[5];

    if (tid < 32) {
        float S = g_es[(size_t)bh * NCHUNK + tid];   // NCHUNK == 32
#pragma unroll
        for (int o = 16; o; o >>= 1) S += __shfl_xor_sync(0xffffffffu, S, o);
        if (tid == 0) sS = S;
    }
    __syncthreads();
    float ginvS = gg / sS;
    float gc = 1.f - gg;

    float* lrow = wbuf + (size_t)bh * N_;
    const float* wprow = wprev + (size_t)bh * N_;

#pragma unroll 4
    for (int i = 0; i < 32; i++) {
        int n = tid + i * 512;
        sw[n] = fmaf(ginvS, lrow[n], gc * wprow[n]);
    }
    __syncthreads();

    float wp[32];
    float lsum = 0.f;
#pragma unroll 4
    for (int i = 0; i < 32; i++) {
        int n = tid + i * 512;
        int nm = (n + N_ - 1) & (N_ - 1);
        int np = (n + 1) & (N_ - 1);
        float ws = s0 * sw[nm] + s1 * sw[n] + s2 * sw[np];
        float v = exp2f(gamma * __log2f(ws));
        wp[i] = v;
        lsum += v;
    }
#pragma unroll
    for (int o = 16; o; o >>= 1) lsum += __shfl_xor_sync(0xffffffffu, lsum, o);
    int w = tid >> 5, l = tid & 31;
    if (l == 0) red[w] = lsum;
    __syncthreads();
    if (w == 0) {
        float v = (l < 16) ? red[l] : 0.f;
#pragma unroll
        for (int o = 8; o; o >>= 1) v += __shfl_xor_sync(0xffffffffu, v, o);
        if (l == 0) red[0] = v;
    }
    __syncthreads();
    float inv = 1.f / (red[0] + 1e-16f);

#pragma unroll 4
    for (int i = 0; i < 32; i++)
        lrow[tid + i * 512] = wp[i] * inv;
}

// ---------------- kernel 5: read partials (whole-chunk w stage) -------------
__global__ __launch_bounds__(256) void k_read(const float* __restrict__ mem,
                                              const float* __restrict__ wbuf) {
    __shared__ float wsh[8][512];            // 16 KB: full chunk of w, all heads
    __shared__ float red[8][512];
    int b = blockIdx.y, chunk = blockIdx.x;
    int tid = threadIdx.x;
    int w = tid >> 5, lane = tid & 31;
    float2 acc[8];
#pragma unroll
    for (int h = 0; h < 8; h++) acc[h] = make_float2(0.f, 0.f);

    const float2* mrow = (const float2*)(mem + ((size_t)b * N_ + (size_t)chunk * CHUNK_N) * M_);

#pragma unroll
    for (int i = 0; i < 16; i++) {
        int idx = tid + i * 256;
        int hh = idx >> 9, nn = idx & 511;
        wsh[hh][nn] = wbuf[((size_t)(b * 8 + hh)) * N_ + chunk * CHUNK_N + nn];
    }
    __syncthreads();

#pragma unroll 4
    for (int j = 0; j < 64; j++) {
        int nl = w * 64 + j;
        float2 mv = mrow[(size_t)nl * 32 + lane];
#pragma unroll
        for (int h = 0; h < 8; h++) {
            float wv = wsh[h][nl];
            acc[h].x = fmaf(wv, mv.x, acc[h].x);
            acc[h].y = fmaf(wv, mv.y, acc[h].y);
        }
    }
    __syncthreads();
#pragma unroll
    for (int h = 0; h < 8; h++) {
        red[w][h * 64 + lane * 2]     = acc[h].x;
        red[w][h * 64 + lane * 2 + 1] = acc[h].y;
    }
    __syncthreads();
#pragma unroll
    for (int r = 0; r < 2; r++) {
        int i = tid + r * 256;
        float s = 0.f;
#pragma unroll
        for (int ww = 0; ww < 8; ww++) s += red[ww][i];
        g_partial[((size_t)chunk * B_ + b) * 512 + i] = s;
    }
}

// ---------------- kernel 6: reduce partials -> read_data --------------------
__global__ __launch_bounds__(256) void k_final(float* __restrict__ out) {
    int i = blockIdx.x * 256 + threadIdx.x;  // < 32768
    float s = 0.f;
#pragma unroll
    for (int c = 0; c < NCHUNK; c++)
        s += g_partial[(size_t)c * BH_ * M_ + i];
    out[i] = s;
}

// ---------------- launch -----------------------------------------------------
extern "C" void kernel_launch(void* const* d_in, const int* in_sizes, int n_in,
                              void* d_out, int out_size) {
    const float* x     = (const float*)d_in[0];
    const float* mem   = (const float*)d_in[1];
    const float* wprev = (const float*)d_in[2];
    const float* W     = (const float*)d_in[3];
    const float* bias  = (const float*)d_in[4];
    float* out = (float*)d_out;
    float* out_read = out;                         // 32768
    float* out_w    = out + 32768;                 // 8388608
    float* out_e    = out + 32768 + (size_t)BH_ * N_;
    float* out_a    = out_e + 32768;

    cudaFuncSetAttribute(k_cos,  cudaFuncAttributeMaxDynamicSharedMemorySize, TILE_R * PITCH * 4);
    cudaFuncSetAttribute(k_addr, cudaFuncAttributeMaxDynamicSharedMemorySize, N_ * 4);

    k_nop<<<1, 32>>>();   // keeps the fixed ncu capture slot on k_cos
    k_gemm<<<dim3(50, KSPLIT), 256>>>(x, W);
    k_act<<<BH_, 64>>>(bias, out_e, out_a);
    k_cos<<<dim3(NCHUNK, B_), 256, TILE_R * PITCH * 4>>>(mem, out_w);
    k_addr<<<BH_, 512, N_ * 4>>>(out_w, wprev);
    k_read<<<dim3(NCHUNK, B_), 256>>>(mem, out_w);
    k_final<<<128, 256>>>(out_read);
}